// round 7
// baseline (speedup 1.0000x reference)
#include <cuda_runtime.h>
#include <cuda_fp16.h>

// Problem constants
#define FX 80
#define NX 128
#define HH 512
#define WW 1024
#define BC 16                 // B*C fused channel count
#define HC 8                  // channels per pipeline stage
#define M  (FX * NX * NX)     // 1310720 texels per channel
#define HW (HH * WW)          // 524288 pixels

// Two half-tables: texel-major, 8 fp16 channels each (16B/texel, 20MB each).
__device__ __align__(128) __half g_xtA[(size_t)M * HC];
__device__ __align__(128) __half g_xtB[(size_t)M * HC];

__device__ __forceinline__ unsigned int h2u(__half2 h) {
    return *reinterpret_cast<unsigned int*>(&h);
}

// ---------------------------------------------------------------------------
// Transpose one 8-channel half: register transpose (proven streaming-roof
// recipe from R3). Triggers PDL completion at entry so the next PSS-launched
// kernel (S_A, which does NOT read this kernel's output) may overlap.
// ---------------------------------------------------------------------------
__global__ void __launch_bounds__(256) transpose_part(const float* __restrict__ x,
                                                      int part) {
#if __CUDA_ARCH__ >= 900
    cudaTriggerProgrammaticLaunchCompletion();
#endif
    const int m = blockIdx.x * 256 + threadIdx.x;   // one texel per thread
    const float* xs = x + (size_t)(part * HC) * M;
    __half* dst = part ? g_xtB : g_xtA;

    float v[HC];
#pragma unroll
    for (int c = 0; c < HC; c++)
        v[c] = __ldg(xs + (size_t)c * M + m);       // 8 independent coalesced LDG.32

    unsigned int w[4];
#pragma unroll
    for (int j = 0; j < 4; j++)
        w[j] = h2u(__floats2half2_rn(v[2 * j], v[2 * j + 1]));

    *reinterpret_cast<uint4*>(dst + (size_t)m * HC) = make_uint4(w[0], w[1], w[2], w[3]);
}

// accumulate 8 fp16 channels (one uint4) into fp32 accumulators with weight w
__device__ __forceinline__ void acc8(float* r, const uint4& a, float w) {
    const __half2* h = reinterpret_cast<const __half2*>(&a);
#pragma unroll
    for (int j = 0; j < 4; j++) {
        float2 f = __half22float2(h[j]);
        r[2 * j]     = fmaf(f.x, w, r[2 * j]);
        r[2 * j + 1] = fmaf(f.y, w, r[2 * j + 1]);
    }
}

// ---------------------------------------------------------------------------
// Sample one 8-channel half: 1 thread per pixel, 4 corner LDG.128 (each 16B
// load is a FULL 8-channel texel row; the u0/u0+1 pair is 32B contiguous).
// Warp = 32 consecutive pixels -> 128B-coalesced stores per channel plane.
// ---------------------------------------------------------------------------
__global__ void __launch_bounds__(256) sample_part(const int*   __restrict__ quad,
                                                   const float* __restrict__ uv,
                                                   float*       __restrict__ out,
                                                   int part) {
    const int pix = blockIdx.x * 256 + threadIdx.x;
    const __half* tab = part ? g_xtB : g_xtA;

    const float2 uvp = reinterpret_cast<const float2*>(uv)[pix];
    const int    f   = quad[pix];

    int u0 = min(max((int)floorf(uvp.x), 0), NX - 2);
    int v0 = min(max((int)floorf(uvp.y), 0), NX - 2);
    const float du = uvp.x - (float)u0;
    const float dv = uvp.y - (float)v0;

    const __half* base = tab + ((size_t)((f * NX + v0) * NX + u0)) * HC;
    const uint4 a00 = *reinterpret_cast<const uint4*>(base);
    const uint4 a01 = *reinterpret_cast<const uint4*>(base + HC);
    const uint4 a10 = *reinterpret_cast<const uint4*>(base + HC * NX);
    const uint4 a11 = *reinterpret_cast<const uint4*>(base + HC * NX + HC);

    const float w00 = (1.0f - du) * (1.0f - dv);
    const float w01 = du * (1.0f - dv);
    const float w10 = (1.0f - du) * dv;
    const float w11 = du * dv;

    float r[HC];
#pragma unroll
    for (int j = 0; j < HC; j++) r[j] = 0.0f;
    acc8(r, a00, w00);
    acc8(r, a01, w01);
    acc8(r, a10, w10);
    acc8(r, a11, w11);

    float* o = out + (size_t)(part * HC) * HW + pix;
#pragma unroll
    for (int k = 0; k < HC; k++)
        o[(size_t)k * HW] = r[k];
}

extern "C" void kernel_launch(void* const* d_in, const int* in_sizes, int n_in,
                              void* d_out, int out_size) {
    const float* x    = (const float*)d_in[0];   // [2,8,80,128,128] fp32
    const int*   quad = (const int*)  d_in[1];   // [512,1024] int32
    const float* uv   = (const float*)d_in[2];   // [512,1024,2] fp32
    float*       out  = (float*)d_out;           // [2,8,512,1024] fp32

    // Chain A then chain B transposes (T_B triggers PDL completion at entry).
    transpose_part<<<M / 256, 256>>>(x, 0);
    transpose_part<<<M / 256, 256>>>(x, 1);

    // S_A: programmatic-stream-serialization launch -> may run CONCURRENTLY
    // with T_B (it only reads table A, fully written before T_B started).
    {
        cudaLaunchConfig_t cfg = {};
        cfg.gridDim  = dim3(HW / 256);
        cfg.blockDim = dim3(256);
        cfg.dynamicSmemBytes = 0;
        cfg.stream = 0;
        cudaLaunchAttribute at[1];
        at[0].id = cudaLaunchAttributeProgrammaticStreamSerialization;
        at[0].val.programmaticStreamSerializationAllowed = 1;
        cfg.attrs = at;
        cfg.numAttrs = 1;
        cudaLaunchKernelEx(&cfg, sample_part, quad, uv, (float*)d_out, 0);
    }

    // S_B: normal launch -> waits for all prior work (T_B and S_A) to finish.
    sample_part<<<HW / 256, 256>>>(quad, uv, out, 1);
}

// round 9
// speedup vs baseline: 1.2252x; 1.2252x over previous
#include <cuda_runtime.h>
#include <cuda_fp16.h>

// Problem constants
#define FX 80
#define NX 128
#define HH 512
#define WW 1024
#define BC 16                 // B*C fused channel count
#define M  (FX * NX * NX)     // 1310720 texels per channel
#define HW (HH * WW)          // 524288 pixels

// Scratch: x transposed + converted to fp16, layout [M][16] halfs (32B/texel).
// 40MB -> stays L2-resident (126MB L2) between the two passes.
__device__ __align__(128) __half g_xt[(size_t)M * BC];

__device__ __forceinline__ unsigned int h2u(__half2 h) {
    return *reinterpret_cast<unsigned int*>(&h);
}

// ---------------------------------------------------------------------------
// Pass 1: fused transpose+convert, register-only (R3/R5 version, measured
// 20.1-20.5us = streaming roof for 120MB). Warp does 16 coalesced scalar
// loads (one per channel); lane t then holds texel (m0+t)'s 16 channels in
// registers -> convert to 8 half2, write 32B via 2 STG.128. MLP=16, no smem.
// ---------------------------------------------------------------------------
__global__ void __launch_bounds__(256) transpose_kernel(const float* __restrict__ x) {
    const int m = blockIdx.x * 256 + threadIdx.x;   // one texel per thread

    float v[16];
#pragma unroll
    for (int c = 0; c < 16; c++)
        v[c] = __ldg(x + (size_t)c * M + m);        // 16 independent coalesced LDG.32

    unsigned int w[8];
#pragma unroll
    for (int j = 0; j < 8; j++)
        w[j] = h2u(__floats2half2_rn(v[2 * j], v[2 * j + 1]));

    uint4* dst = reinterpret_cast<uint4*>(g_xt + (size_t)m * BC);
    dst[0] = make_uint4(w[0], w[1], w[2], w[3]);
    dst[1] = make_uint4(w[4], w[5], w[6], w[7]);
}

// accumulate 8 fp16 channels (one uint4) into fp32 accumulators with weight w
__device__ __forceinline__ void acc8(float* r, const uint4& a, float w) {
    const __half2* h = reinterpret_cast<const __half2*>(&a);
#pragma unroll
    for (int j = 0; j < 4; j++) {
        float2 f = __half22float2(h[j]);
        r[2 * j]     = fmaf(f.x, w, r[2 * j]);
        r[2 * j + 1] = fmaf(f.y, w, r[2 * j + 1]);
    }
}

// ---------------------------------------------------------------------------
// Pass 2: bilinear gather (R4 version, measured 17.6us = best of 5 variants).
// Block = 256 threads = 128 pixels x 2 half-groups. Each thread: 4
// independent LDG.128 (16B = 8 fp16 channels per corner). Direct stores:
// 16 lanes of same hg cover 16 consecutive pixels -> fully-used 64B
// segments per channel plane per warp. No smem, no barriers.
// ---------------------------------------------------------------------------
__global__ void __launch_bounds__(256) sample_kernel(const int*   __restrict__ quad,
                                                     const float* __restrict__ uv,
                                                     float*       __restrict__ out) {
    const int t   = threadIdx.x;
    const int p   = t >> 1;            // pixel-in-tile 0..127
    const int hg  = t & 1;             // half-group: channels hg*8 .. hg*8+7
    const int pix = blockIdx.x * 128 + p;

    const float2 uvp = reinterpret_cast<const float2*>(uv)[pix];
    const int    f   = quad[pix];

    int u0 = min(max((int)floorf(uvp.x), 0), NX - 2);
    int v0 = min(max((int)floorf(uvp.y), 0), NX - 2);
    const float du = uvp.x - (float)u0;
    const float dv = uvp.y - (float)v0;

    const __half* base = g_xt + ((size_t)((f * NX + v0) * NX + u0)) * BC + hg * 8;
    const uint4 a00 = *reinterpret_cast<const uint4*>(base);
    const uint4 a01 = *reinterpret_cast<const uint4*>(base + BC);
    const uint4 a10 = *reinterpret_cast<const uint4*>(base + BC * NX);
    const uint4 a11 = *reinterpret_cast<const uint4*>(base + BC * NX + BC);

    const float w00 = (1.0f - du) * (1.0f - dv);
    const float w01 = du * (1.0f - dv);
    const float w10 = (1.0f - du) * dv;
    const float w11 = du * dv;

    float r[8];
#pragma unroll
    for (int j = 0; j < 8; j++) r[j] = 0.0f;
    acc8(r, a00, w00);
    acc8(r, a01, w01);
    acc8(r, a10, w10);
    acc8(r, a11, w11);

    // direct coalesced stores: 16 lanes of same hg -> 16 consecutive pixels
    float* o = out + (size_t)(hg * 8) * HW + pix;
#pragma unroll
    for (int k = 0; k < 8; k++)
        o[(size_t)k * HW] = r[k];
}

extern "C" void kernel_launch(void* const* d_in, const int* in_sizes, int n_in,
                              void* d_out, int out_size) {
    const float* x    = (const float*)d_in[0];   // [2,8,80,128,128] fp32
    const int*   quad = (const int*)  d_in[1];   // [512,1024] int32
    const float* uv   = (const float*)d_in[2];   // [512,1024,2] fp32
    float*       out  = (float*)d_out;           // [2,8,512,1024] fp32

    transpose_kernel<<<M / 256, 256>>>(x);            // 5120 blocks
    sample_kernel<<<HW / 128, 256>>>(quad, uv, out);  // 4096 blocks
}